// round 3
// baseline (speedup 1.0000x reference)
#include <cuda_runtime.h>
#include <cstdint>

// x (4,2048,4096) f32, kernel (4096,16384) f32, bias (16384) f32 -> out (4,2048,16384) f32
#define M_TOK   8192
#define D_DIM   4096
#define F_DIM   16384
#define F32_EPS 1.1920929e-07f
#define NKT     32            // 4096 / 128 bytes per k-iter

// s8 encodings of +1 / -1
#define S8_P1 0x01u
#define S8_N1 0xFFu

// ---------------- static device scratch ----------------
__device__ __align__(16) uint8_t g_Xq[(size_t)M_TOK * D_DIM];   // [token][d] s8 ±1
__device__ __align__(16) uint8_t g_Kq[(size_t)F_DIM * D_DIM];   // [feat][d]  s8 ±1
__device__ float g_bx[M_TOK];
__device__ float g_bk[F_DIM];
__device__ float g_bkpart[32][F_DIM];

__device__ __forceinline__ uint32_t smem_u32(const void* p) {
    uint32_t a;
    asm("{ .reg .u64 t; cvta.to.shared.u64 t, %1; cvt.u32.u64 %0, t; }" : "=r"(a) : "l"(p));
    return a;
}
__device__ __forceinline__ uint32_t sw128(uint32_t off) { return off ^ ((off >> 3) & 0x70u); }

__device__ __forceinline__ void cp16(uint32_t dst, const void* src) {
    asm volatile("cp.async.cg.shared.global [%0], [%1], 16;" :: "r"(dst), "l"(src));
}
__device__ __forceinline__ void ldsm4(uint32_t& r0, uint32_t& r1, uint32_t& r2, uint32_t& r3,
                                      uint32_t addr) {
    asm volatile("ldmatrix.sync.aligned.m8n8.x4.shared.b16 {%0,%1,%2,%3}, [%4];"
                 : "=r"(r0), "=r"(r1), "=r"(r2), "=r"(r3) : "r"(addr));
}
__device__ __forceinline__ void mma_s8(int* c, uint32_t a0, uint32_t a1, uint32_t a2, uint32_t a3,
                                       uint32_t b0, uint32_t b1) {
    asm volatile("mma.sync.aligned.m16n8k32.row.col.s32.s8.s8.s32 "
                 "{%0,%1,%2,%3}, {%4,%5,%6,%7}, {%8,%9}, {%0,%1,%2,%3};"
                 : "+r"(c[0]), "+r"(c[1]), "+r"(c[2]), "+r"(c[3])
                 : "r"(a0), "r"(a1), "r"(a2), "r"(a3), "r"(b0), "r"(b1));
}

// ---------------------------------------------------------------------------
// Pass A: per-token max|x| + s8 sign pack. One warp per token.
// ---------------------------------------------------------------------------
__global__ void pack_x_kernel(const float* __restrict__ x) {
    int token = blockIdx.x * (blockDim.x >> 5) + (threadIdx.x >> 5);
    int lane  = threadIdx.x & 31;
    const float4* row = (const float4*)(x + (size_t)token * D_DIM);
    uint8_t* qrow = g_Xq + (size_t)token * D_DIM;
    float m = 0.f;
    #pragma unroll 8
    for (int c = 0; c < 32; ++c) {
        float4 v = row[c * 32 + lane];
        m = fmaxf(m, fmaxf(fmaxf(fabsf(v.x), fabsf(v.y)), fmaxf(fabsf(v.z), fabsf(v.w))));
        uint32_t b = (v.x < 0.f ? S8_N1 : S8_P1)
                   | ((v.y < 0.f ? S8_N1 : S8_P1) << 8)
                   | ((v.z < 0.f ? S8_N1 : S8_P1) << 16)
                   | ((v.w < 0.f ? S8_N1 : S8_P1) << 24);
        *(uint32_t*)(qrow + c * 128 + lane * 4) = b;
    }
    #pragma unroll
    for (int o = 16; o; o >>= 1) m = fmaxf(m, __shfl_xor_sync(0xffffffffu, m, o));
    if (lane == 0) g_bx[token] = m + F32_EPS;
}

// ---------------------------------------------------------------------------
// Pass B: transpose K (d,f)->(f,d) sign pack + per-feature partial max.
// ---------------------------------------------------------------------------
__global__ __launch_bounds__(256)
void pack_k_kernel(const float* __restrict__ kern) {
    __shared__ uint8_t T[128 * 132];
    __shared__ float smax[128];
    const int tid = threadIdx.x;
    const int f0 = blockIdx.x * 128, d0 = blockIdx.y * 128;
    if (tid < 128) smax[tid] = 0.f;
    __syncthreads();

    const int fq = tid & 31;
    float m0 = 0.f, m1 = 0.f, m2 = 0.f, m3 = 0.f;
    #pragma unroll 4
    for (int i = 0; i < 16; ++i) {
        int dr = i * 8 + (tid >> 5);
        float4 v = *(const float4*)(kern + (size_t)(d0 + dr) * F_DIM + f0 + fq * 4);
        m0 = fmaxf(m0, fabsf(v.x)); m1 = fmaxf(m1, fabsf(v.y));
        m2 = fmaxf(m2, fabsf(v.z)); m3 = fmaxf(m3, fabsf(v.w));
        T[(fq * 4 + 0) * 132 + dr] = v.x < 0.f ? S8_N1 : S8_P1;
        T[(fq * 4 + 1) * 132 + dr] = v.y < 0.f ? S8_N1 : S8_P1;
        T[(fq * 4 + 2) * 132 + dr] = v.z < 0.f ? S8_N1 : S8_P1;
        T[(fq * 4 + 3) * 132 + dr] = v.w < 0.f ? S8_N1 : S8_P1;
    }
    atomicMax((int*)&smax[fq * 4 + 0], __float_as_int(m0));
    atomicMax((int*)&smax[fq * 4 + 1], __float_as_int(m1));
    atomicMax((int*)&smax[fq * 4 + 2], __float_as_int(m2));
    atomicMax((int*)&smax[fq * 4 + 3], __float_as_int(m3));
    __syncthreads();

    #pragma unroll 4
    for (int i = 0; i < 16; ++i) {
        int idx = i * 256 + tid;
        int fr = idx >> 5, wq = idx & 31;
        uint32_t w = *(uint32_t*)&T[fr * 132 + wq * 4];
        *(uint32_t*)(g_Kq + (size_t)(f0 + fr) * D_DIM + d0 + wq * 4) = w;
    }
    if (tid < 128) g_bkpart[blockIdx.y][f0 + tid] = smax[tid];
}

__global__ void reduce_bk_kernel() {
    int f = blockIdx.x * blockDim.x + threadIdx.x;
    float m = 0.f;
    #pragma unroll
    for (int s = 0; s < 32; ++s) m = fmaxf(m, g_bkpart[s][f]);
    g_bk[f] = m + F32_EPS;
}

// ---------------------------------------------------------------------------
// Pass C: s8 mma.sync GEMM. Block 128x128, k-iter 128 bytes, double-buffered
// cp.async, SW128 smem (conflict-free ldmatrix), 8 warps in 2(m) x 4(n),
// warp tile 64x32 (4 m-frags x 4 n-frags of m16n8k32).
// ---------------------------------------------------------------------------
#define STAGE_BYTES 16384

__global__ __launch_bounds__(256)
void imma_gemm_kernel(const float* __restrict__ bias, float* __restrict__ out) {
    extern __shared__ uint8_t smem[];
    const uint32_t sA = smem_u32(smem);            // 2 stages x 16KB
    const uint32_t sB = sA + 2 * STAGE_BYTES;      // 2 stages x 16KB
    const int tid = threadIdx.x, wid = tid >> 5, lane = tid & 31;
    const int wm = wid & 1, wn = wid >> 1;
    const int f0 = blockIdx.x * 128;
    const int t0 = blockIdx.y * 128;

    const uint8_t* __restrict__ gA = g_Xq + (size_t)t0 * D_DIM;
    const uint8_t* __restrict__ gB = g_Kq + (size_t)f0 * D_DIM;

    int acc[4][4][4];
    #pragma unroll
    for (int mi = 0; mi < 4; ++mi)
        #pragma unroll
        for (int ni = 0; ni < 4; ++ni)
            #pragma unroll
            for (int r = 0; r < 4; ++r) acc[mi][ni][r] = 0;

    // precomputed fill indices
    const int fr = tid >> 3;                // row 0..31 (+i*32)
    const int fc = (tid & 7) << 4;          // 16B quadrant

    auto fill = [&](int kt, int st) {
        const uint32_t da = sA + st * STAGE_BYTES;
        const uint32_t db = sB + st * STAGE_BYTES;
        #pragma unroll
        for (int i = 0; i < 4; ++i) {
            int r = fr + i * 32;
            uint32_t so = sw128(r * 128 + fc);
            cp16(da + so, gA + (size_t)r * D_DIM + kt * 128 + fc);
            cp16(db + so, gB + (size_t)r * D_DIM + kt * 128 + fc);
        }
        asm volatile("cp.async.commit_group;" ::: "memory");
    };

    fill(0, 0);

    const int arow = wm * 64 + (lane & 15);
    const int brow = wn * 32 + (lane & 15);
    const int khalf = (lane & 16);           // 0 or 16

    for (int kt = 0; kt < NKT; ++kt) {
        if (kt < NKT - 1) {
            fill(kt + 1, (kt + 1) & 1);
            asm volatile("cp.async.wait_group 1;" ::: "memory");
        } else {
            asm volatile("cp.async.wait_group 0;" ::: "memory");
        }
        __syncthreads();

        const uint32_t aSt = sA + (kt & 1) * STAGE_BYTES;
        const uint32_t bSt = sB + (kt & 1) * STAGE_BYTES;

        #pragma unroll
        for (int ks = 0; ks < 4; ++ks) {
            const int kcol = ks * 32 + khalf;
            uint32_t b[4][2];
            #pragma unroll
            for (int nj = 0; nj < 2; ++nj) {
                uint32_t r0, r1, r2, r3;
                ldsm4(r0, r1, r2, r3, bSt + sw128((brow + nj * 16) * 128 + kcol));
                b[2 * nj][0] = r0; b[2 * nj + 1][0] = r1;
                b[2 * nj][1] = r2; b[2 * nj + 1][1] = r3;
            }
            #pragma unroll
            for (int mi = 0; mi < 4; ++mi) {
                uint32_t a0, a1, a2, a3;
                ldsm4(a0, a1, a2, a3, aSt + sw128((arow + mi * 16) * 128 + kcol));
                #pragma unroll
                for (int ni = 0; ni < 4; ++ni)
                    mma_s8(acc[mi][ni], a0, a1, a2, a3, b[ni][0], b[ni][1]);
            }
        }
        __syncthreads();
    }

    // Epilogue: c0,c1 at (row=L/4, col=2*(L%4)), c2,c3 at row+8.
    const int lrow = lane >> 2;
    const int lcol = (lane & 3) * 2;
    const int rbase = t0 + wm * 64;
    const int cbase = f0 + wn * 32;

    float sxa[4][2];
    #pragma unroll
    for (int mi = 0; mi < 4; ++mi) {
        sxa[mi][0] = 0.25f * g_bx[rbase + mi * 16 + lrow];
        sxa[mi][1] = 0.25f * g_bx[rbase + mi * 16 + lrow + 8];
    }
    float bk0[4], bk1[4], bs0[4], bs1[4];
    #pragma unroll
    for (int ni = 0; ni < 4; ++ni) {
        int c = cbase + ni * 8 + lcol;
        bk0[ni] = g_bk[c];     bk1[ni] = g_bk[c + 1];
        bs0[ni] = bias[c];     bs1[ni] = bias[c + 1];
    }

    #pragma unroll
    for (int mi = 0; mi < 4; ++mi) {
        #pragma unroll
        for (int ni = 0; ni < 4; ++ni) {
            int c = cbase + ni * 8 + lcol;
            float2 v0, v1;
            v0.x = fmaf(sxa[mi][0] * bk0[ni], (float)acc[mi][ni][0], bs0[ni]);
            v0.y = fmaf(sxa[mi][0] * bk1[ni], (float)acc[mi][ni][1], bs1[ni]);
            v1.x = fmaf(sxa[mi][1] * bk0[ni], (float)acc[mi][ni][2], bs0[ni]);
            v1.y = fmaf(sxa[mi][1] * bk1[ni], (float)acc[mi][ni][3], bs1[ni]);
            *(float2*)(out + (size_t)(rbase + mi * 16 + lrow) * F_DIM + c) = v0;
            *(float2*)(out + (size_t)(rbase + mi * 16 + lrow + 8) * F_DIM + c) = v1;
        }
    }
}

// ---------------------------------------------------------------------------
extern "C" void kernel_launch(void* const* d_in, const int* in_sizes, int n_in,
                              void* d_out, int out_size) {
    const float* x    = (const float*)d_in[0];
    const float* kern = (const float*)d_in[1];
    const float* bias = (const float*)d_in[2];
    float* out = (float*)d_out;

    pack_x_kernel<<<M_TOK / 8, 256>>>(x);
    dim3 gk(F_DIM / 128, D_DIM / 128);
    pack_k_kernel<<<gk, 256>>>(kern);
    reduce_bk_kernel<<<F_DIM / 256, 256>>>();

    cudaFuncSetAttribute(imma_gemm_kernel,
                         cudaFuncAttributeMaxDynamicSharedMemorySize, 4 * STAGE_BYTES);
    dim3 gg(F_DIM / 128, M_TOK / 128);
    imma_gemm_kernel<<<gg, 256, 4 * STAGE_BYTES>>>(bias, out);
}

// round 4
// speedup vs baseline: 2.0202x; 2.0202x over previous
#include <cuda_runtime.h>
#include <cstdint>

// x (4,2048,4096) f32, kernel (4096,16384) f32, bias (16384) f32 -> out (4,2048,16384) f32
#define M_TOK   8192
#define D_DIM   4096
#define F_DIM   16384
#define NCHUNK  128           // 4096 bits / 32
#define F32_EPS 1.1920929e-07f

#define S8_P1 0x01u
#define S8_N1 0xFFu

// Tile bookkeeping: 64 x 128 = 8192 tiles of 128x128.
// Blocks with (flat % 15) < 4 run IMMA (tensor pipe), else popcount (ALU pipe).
// 8192 = 15*546 + 2  ->  imma tiles = 546*4 + 2 = 2186, popc tiles = 6006.
#define N_TILES    8192
#define IMMA_TILES 2186

// ---------------- static device scratch ----------------
__device__ __align__(16) uint8_t  g_Xq[(size_t)M_TOK * D_DIM];     // s8 ±1 [token][d]
__device__ __align__(16) uint8_t  g_Kq[(size_t)F_DIM * D_DIM];     // s8 ±1 [feat][d]
__device__ __align__(16) uint32_t g_Xbits[NCHUNK * M_TOK];         // [chunk][token]
__device__ __align__(16) uint32_t g_Kbits[NCHUNK * F_DIM];         // [chunk][feature]
__device__ float g_bx[M_TOK];
__device__ float g_bk[F_DIM];
__device__ float g_bkpart[32][F_DIM];

__device__ __forceinline__ uint32_t smem_u32(const void* p) {
    uint32_t a;
    asm("{ .reg .u64 t; cvta.to.shared.u64 t, %1; cvt.u32.u64 %0, t; }" : "=r"(a) : "l"(p));
    return a;
}
__device__ __forceinline__ uint32_t sw128(uint32_t off) { return off ^ ((off >> 3) & 0x70u); }
__device__ __forceinline__ void cp16(uint32_t dst, const void* src) {
    asm volatile("cp.async.cg.shared.global [%0], [%1], 16;" :: "r"(dst), "l"(src));
}
__device__ __forceinline__ void ldsm4(uint32_t& r0, uint32_t& r1, uint32_t& r2, uint32_t& r3,
                                      uint32_t addr) {
    asm volatile("ldmatrix.sync.aligned.m8n8.x4.shared.b16 {%0,%1,%2,%3}, [%4];"
                 : "=r"(r0), "=r"(r1), "=r"(r2), "=r"(r3) : "r"(addr));
}
__device__ __forceinline__ void mma_s8(int* c, uint32_t a0, uint32_t a1, uint32_t a2, uint32_t a3,
                                       uint32_t b0, uint32_t b1) {
    asm volatile("mma.sync.aligned.m16n8k32.row.col.s32.s8.s8.s32 "
                 "{%0,%1,%2,%3}, {%4,%5,%6,%7}, {%8,%9}, {%0,%1,%2,%3};"
                 : "+r"(c[0]), "+r"(c[1]), "+r"(c[2]), "+r"(c[3])
                 : "r"(a0), "r"(a1), "r"(a2), "r"(a3), "r"(b0), "r"(b1));
}

// ---------------------------------------------------------------------------
// Pack passes
// ---------------------------------------------------------------------------
__global__ void pack_x_s8_kernel(const float* __restrict__ x) {
    int token = blockIdx.x * (blockDim.x >> 5) + (threadIdx.x >> 5);
    int lane  = threadIdx.x & 31;
    const float4* row = (const float4*)(x + (size_t)token * D_DIM);
    uint8_t* qrow = g_Xq + (size_t)token * D_DIM;
    float m = 0.f;
    #pragma unroll 8
    for (int c = 0; c < 32; ++c) {
        float4 v = row[c * 32 + lane];
        m = fmaxf(m, fmaxf(fmaxf(fabsf(v.x), fabsf(v.y)), fmaxf(fabsf(v.z), fabsf(v.w))));
        uint32_t b = (v.x < 0.f ? S8_N1 : S8_P1)
                   | ((v.y < 0.f ? S8_N1 : S8_P1) << 8)
                   | ((v.z < 0.f ? S8_N1 : S8_P1) << 16)
                   | ((v.w < 0.f ? S8_N1 : S8_P1) << 24);
        *(uint32_t*)(qrow + c * 128 + lane * 4) = b;
    }
    #pragma unroll
    for (int o = 16; o; o >>= 1) m = fmaxf(m, __shfl_xor_sync(0xffffffffu, m, o));
    if (lane == 0) g_bx[token] = m + F32_EPS;
}

__global__ void pack_x_bits_kernel(const float* __restrict__ x) {
    int token = blockIdx.x * (blockDim.x >> 5) + (threadIdx.x >> 5);
    int lane  = threadIdx.x & 31;
    const float* row = x + (size_t)token * D_DIM;
    #pragma unroll 4
    for (int c = 0; c < NCHUNK; ++c) {
        float v = row[c * 32 + lane];
        unsigned w = __ballot_sync(0xffffffffu, v < 0.f);
        if (lane == 0) g_Xbits[c * M_TOK + token] = w;
    }
}

__global__ __launch_bounds__(256)
void pack_k_s8_kernel(const float* __restrict__ kern) {
    __shared__ uint8_t T[128 * 132];
    __shared__ float smax[128];
    const int tid = threadIdx.x;
    const int f0 = blockIdx.x * 128, d0 = blockIdx.y * 128;
    if (tid < 128) smax[tid] = 0.f;
    __syncthreads();

    const int fq = tid & 31;
    float m0 = 0.f, m1 = 0.f, m2 = 0.f, m3 = 0.f;
    #pragma unroll 4
    for (int i = 0; i < 16; ++i) {
        int dr = i * 8 + (tid >> 5);
        float4 v = *(const float4*)(kern + (size_t)(d0 + dr) * F_DIM + f0 + fq * 4);
        m0 = fmaxf(m0, fabsf(v.x)); m1 = fmaxf(m1, fabsf(v.y));
        m2 = fmaxf(m2, fabsf(v.z)); m3 = fmaxf(m3, fabsf(v.w));
        T[(fq * 4 + 0) * 132 + dr] = v.x < 0.f ? S8_N1 : S8_P1;
        T[(fq * 4 + 1) * 132 + dr] = v.y < 0.f ? S8_N1 : S8_P1;
        T[(fq * 4 + 2) * 132 + dr] = v.z < 0.f ? S8_N1 : S8_P1;
        T[(fq * 4 + 3) * 132 + dr] = v.w < 0.f ? S8_N1 : S8_P1;
    }
    atomicMax((int*)&smax[fq * 4 + 0], __float_as_int(m0));
    atomicMax((int*)&smax[fq * 4 + 1], __float_as_int(m1));
    atomicMax((int*)&smax[fq * 4 + 2], __float_as_int(m2));
    atomicMax((int*)&smax[fq * 4 + 3], __float_as_int(m3));
    __syncthreads();

    #pragma unroll 4
    for (int i = 0; i < 16; ++i) {
        int idx = i * 256 + tid;
        int fr = idx >> 5, wq = idx & 31;
        uint32_t w = *(uint32_t*)&T[fr * 132 + wq * 4];
        *(uint32_t*)(g_Kq + (size_t)(f0 + fr) * D_DIM + d0 + wq * 4) = w;
    }
    if (tid < 128) g_bkpart[blockIdx.y][f0 + tid] = smax[tid];
}

__global__ void pack_k_bits_kernel(const float* __restrict__ kern) {
    int f   = blockIdx.x * blockDim.x + threadIdx.x;
    int seg = blockIdx.y;                // 16 segments of 8 chunks
    int c0  = seg * 8;
    for (int c = 0; c < 8; ++c) {
        const float* p = kern + (size_t)((c0 + c) * 32) * F_DIM + f;
        unsigned w = 0;
        #pragma unroll
        for (int i = 0; i < 32; ++i)
            w |= ((p[(size_t)i * F_DIM] < 0.f) ? 1u : 0u) << i;
        g_Kbits[(c0 + c) * F_DIM + f] = w;
    }
}

__global__ void reduce_bk_kernel() {
    int f = blockIdx.x * blockDim.x + threadIdx.x;
    float m = 0.f;
    #pragma unroll
    for (int s = 0; s < 32; ++s) m = fmaxf(m, g_bkpart[s][f]);
    g_bk[f] = m + F32_EPS;
}

// ---------------------------------------------------------------------------
// Hybrid GEMM: one grid, two block personalities sharing the chip's pipes.
//   IMMA blocks : s8 mma.sync, 128x128 tile, double-buffered cp.async
//   POPC blocks : XOR+POPC,    128x128 tile, double-buffered cp.async
// Dynamic smem = 64KB (imma: 2x16KB A + 2x16KB B; popc: 2x(8KB X + 8KB K)).
// ---------------------------------------------------------------------------
#define STG 16384

__global__ __launch_bounds__(256, 2)
void hybrid_gemm_kernel(const float* __restrict__ bias, float* __restrict__ out) {
    extern __shared__ uint8_t smem[];
    const uint32_t sb = smem_u32(smem);
    const int tid = threadIdx.x, wid = tid >> 5, lane = tid & 31;

    const int flat = blockIdx.x;
    const int k15 = flat / 15, r15 = flat % 15;
    const bool is_imma = (r15 < 4);
    const int tile = is_imma ? (k15 * 4 + r15) : (IMMA_TILES + k15 * 11 + (r15 - 4));
    const int f0 = (tile & 127) * 128;
    const int t0 = (tile >> 7) * 128;

    if (is_imma) {
        // ----------------- tensor-pipe path -----------------
        const uint32_t sA = sb;                 // 2 x 16KB
        const uint32_t sB = sb + 2 * STG;       // 2 x 16KB
        const int wm = wid & 1, wn = wid >> 1;
        const uint8_t* __restrict__ gA = g_Xq + (size_t)t0 * D_DIM;
        const uint8_t* __restrict__ gB = g_Kq + (size_t)f0 * D_DIM;

        int acc[4][4][4];
        #pragma unroll
        for (int mi = 0; mi < 4; ++mi)
            #pragma unroll
            for (int ni = 0; ni < 4; ++ni)
                #pragma unroll
                for (int r = 0; r < 4; ++r) acc[mi][ni][r] = 0;

        const int fr = tid >> 3;
        const int fc = (tid & 7) << 4;

        auto fill = [&](int kt, int st) {
            const uint32_t da = sA + st * STG;
            const uint32_t db = sB + st * STG;
            #pragma unroll
            for (int i = 0; i < 4; ++i) {
                int r = fr + i * 32;
                uint32_t so = sw128(r * 128 + fc);
                cp16(da + so, gA + (size_t)r * D_DIM + kt * 128 + fc);
                cp16(db + so, gB + (size_t)r * D_DIM + kt * 128 + fc);
            }
            asm volatile("cp.async.commit_group;" ::: "memory");
        };

        fill(0, 0);
        const int arow = wm * 64 + (lane & 15);
        const int brow = wn * 32 + (lane & 15);
        const int khalf = (lane & 16);

        for (int kt = 0; kt < 32; ++kt) {
            if (kt < 31) {
                fill(kt + 1, (kt + 1) & 1);
                asm volatile("cp.async.wait_group 1;" ::: "memory");
            } else {
                asm volatile("cp.async.wait_group 0;" ::: "memory");
            }
            __syncthreads();
            const uint32_t aSt = sA + (kt & 1) * STG;
            const uint32_t bSt = sB + (kt & 1) * STG;
            #pragma unroll
            for (int ks = 0; ks < 4; ++ks) {
                const int kcol = ks * 32 + khalf;
                uint32_t b[4][2];
                #pragma unroll
                for (int nj = 0; nj < 2; ++nj) {
                    uint32_t r0, r1, r2, r3;
                    ldsm4(r0, r1, r2, r3, bSt + sw128((brow + nj * 16) * 128 + kcol));
                    b[2 * nj][0] = r0; b[2 * nj + 1][0] = r1;
                    b[2 * nj][1] = r2; b[2 * nj + 1][1] = r3;
                }
                #pragma unroll
                for (int mi = 0; mi < 4; ++mi) {
                    uint32_t a0, a1, a2, a3;
                    ldsm4(a0, a1, a2, a3, aSt + sw128((arow + mi * 16) * 128 + kcol));
                    #pragma unroll
                    for (int ni = 0; ni < 4; ++ni)
                        mma_s8(acc[mi][ni], a0, a1, a2, a3, b[ni][0], b[ni][1]);
                }
            }
            __syncthreads();
        }

        const int lrow = lane >> 2;
        const int lcol = (lane & 3) * 2;
        const int rbase = t0 + wm * 64;
        const int cbase = f0 + wn * 32;

        float sxa[4][2];
        #pragma unroll
        for (int mi = 0; mi < 4; ++mi) {
            sxa[mi][0] = 0.25f * g_bx[rbase + mi * 16 + lrow];
            sxa[mi][1] = 0.25f * g_bx[rbase + mi * 16 + lrow + 8];
        }
        #pragma unroll
        for (int mi = 0; mi < 4; ++mi) {
            #pragma unroll
            for (int ni = 0; ni < 4; ++ni) {
                int c = cbase + ni * 8 + lcol;
                float k0v = g_bk[c], k1v = g_bk[c + 1];
                float b0v = bias[c], b1v = bias[c + 1];
                float2 v0, v1;
                v0.x = fmaf(sxa[mi][0] * k0v, (float)acc[mi][ni][0], b0v);
                v0.y = fmaf(sxa[mi][0] * k1v, (float)acc[mi][ni][1], b1v);
                v1.x = fmaf(sxa[mi][1] * k0v, (float)acc[mi][ni][2], b0v);
                v1.y = fmaf(sxa[mi][1] * k1v, (float)acc[mi][ni][3], b1v);
                *(float2*)(out + (size_t)(rbase + mi * 16 + lrow) * F_DIM + c) = v0;
                *(float2*)(out + (size_t)(rbase + mi * 16 + lrow + 8) * F_DIM + c) = v1;
            }
        }
    } else {
        // ----------------- ALU-pipe path (XOR+POPC) -----------------
        // stage s: X tile [16][128]u32 at s*16KB, K tile at s*16KB + 8KB
        const int wr = wid & 3, wc = wid >> 2;
        const int lr = lane >> 3, lc = lane & 7;
        const int row0 = wr * 32 + lr * 8;
        const int col0 = wc * 64 + lc * 8;

        int acc[8][8];
        #pragma unroll
        for (int i = 0; i < 8; ++i)
            #pragma unroll
            for (int j = 0; j < 8; ++j) acc[i][j] = 0;

        auto fillP = [&](int k0, int st) {
            const uint32_t base = sb + st * STG;
            #pragma unroll
            for (int i = 0; i < 2; ++i) {
                int idx = i * 256 + tid;          // 0..511
                int k = idx >> 5, q = idx & 31;
                cp16(base + k * 512 + q * 16,
                     g_Xbits + (size_t)(k0 + k) * M_TOK + t0 + q * 4);
                cp16(base + 8192 + k * 512 + q * 16,
                     g_Kbits + (size_t)(k0 + k) * F_DIM + f0 + q * 4);
            }
            asm volatile("cp.async.commit_group;" ::: "memory");
        };

        fillP(0, 0);
        for (int it = 0; it < 8; ++it) {          // 8 iters x 16 chunks
            if (it < 7) {
                fillP((it + 1) * 16, (it + 1) & 1);
                asm volatile("cp.async.wait_group 1;" ::: "memory");
            } else {
                asm volatile("cp.async.wait_group 0;" ::: "memory");
            }
            __syncthreads();
            const uint32_t base = sb + (it & 1) * STG;
            #pragma unroll
            for (int k = 0; k < 16; ++k) {
                uint32_t xa[8], kb[8];
                *(uint4*)&xa[0] = *(const uint4*)(smem + (base - sb) + k * 512 + row0 * 4);
                *(uint4*)&xa[4] = *(const uint4*)(smem + (base - sb) + k * 512 + row0 * 4 + 16);
                *(uint4*)&kb[0] = *(const uint4*)(smem + (base - sb) + 8192 + k * 512 + col0 * 4);
                *(uint4*)&kb[4] = *(const uint4*)(smem + (base - sb) + 8192 + k * 512 + col0 * 4 + 16);
                #pragma unroll
                for (int i = 0; i < 8; ++i)
                    #pragma unroll
                    for (int j = 0; j < 8; ++j)
                        acc[i][j] += __popc(xa[i] ^ kb[j]);
            }
            __syncthreads();
        }

        const int trow = t0 + row0;
        const int tcol = f0 + col0;
        float bx4[8], bk4[8], bsv[8];
        #pragma unroll
        for (int i = 0; i < 8; ++i) bx4[i] = 0.25f * g_bx[trow + i];
        #pragma unroll
        for (int j = 0; j < 8; ++j) bk4[j] = g_bk[tcol + j];
        #pragma unroll
        for (int j = 0; j < 8; ++j) bsv[j] = bias[tcol + j];

        #pragma unroll
        for (int i = 0; i < 8; ++i) {
            float r[8];
            #pragma unroll
            for (int j = 0; j < 8; ++j) {
                float dot = (float)(D_DIM - 2 * acc[i][j]);
                r[j] = fmaf(bx4[i] * bk4[j], dot, bsv[j]);
            }
            float* po = out + (size_t)(trow + i) * F_DIM + tcol;
            *(float4*)(po)     = make_float4(r[0], r[1], r[2], r[3]);
            *(float4*)(po + 4) = make_float4(r[4], r[5], r[6], r[7]);
        }
    }
}

// ---------------------------------------------------------------------------
extern "C" void kernel_launch(void* const* d_in, const int* in_sizes, int n_in,
                              void* d_out, int out_size) {
    const float* x    = (const float*)d_in[0];
    const float* kern = (const float*)d_in[1];
    const float* bias = (const float*)d_in[2];
    float* out = (float*)d_out;

    pack_x_s8_kernel<<<M_TOK / 8, 256>>>(x);
    pack_x_bits_kernel<<<M_TOK / 8, 256>>>(x);

    dim3 gk(F_DIM / 128, D_DIM / 128);
    pack_k_s8_kernel<<<gk, 256>>>(kern);
    dim3 gkb(F_DIM / 256, 16);
    pack_k_bits_kernel<<<gkb, 256>>>(kern);
    reduce_bk_kernel<<<F_DIM / 256, 256>>>();

    cudaFuncSetAttribute(hybrid_gemm_kernel,
                         cudaFuncAttributeMaxDynamicSharedMemorySize, 4 * STG);
    hybrid_gemm_kernel<<<N_TILES, 256, 4 * STG>>>(bias, out);
}

// round 5
// speedup vs baseline: 2.4057x; 1.1908x over previous
#include <cuda_runtime.h>
#include <cstdint>

// x (4,2048,4096) f32, kernel (4096,16384) f32, bias (16384) f32 -> out (4,2048,16384) f32
#define M_TOK   8192
#define D_DIM   4096
#define F_DIM   16384
#define NCHUNK  128
#define F32_EPS 1.1920929e-07f

#define S8_P1 0x01u
#define S8_N1 0xFFu

// ---------------- static device scratch ----------------
__device__ __align__(16) uint8_t  g_Xq[(size_t)M_TOK * D_DIM];   // s8 ±1 [token][d]
__device__ __align__(16) uint8_t  g_Kq[(size_t)F_DIM * D_DIM];   // s8 ±1 [feat][d]
__device__ __align__(16) uint32_t g_Xbits[NCHUNK * M_TOK];       // [chunk][token]
__device__ __align__(16) uint32_t g_Kbits[NCHUNK * F_DIM];       // [chunk][feature]
__device__ float g_bx[M_TOK];
__device__ float g_bk[F_DIM];
__device__ float g_bkpart[32][F_DIM];

__device__ __forceinline__ uint32_t smem_u32(const void* p) {
    uint32_t a;
    asm("{ .reg .u64 t; cvta.to.shared.u64 t, %1; cvt.u32.u64 %0, t; }" : "=r"(a) : "l"(p));
    return a;
}
__device__ __forceinline__ uint32_t sw128(uint32_t off) { return off ^ ((off >> 3) & 0x70u); }
__device__ __forceinline__ void cp16(uint32_t dst, const void* src) {
    asm volatile("cp.async.cg.shared.global [%0], [%1], 16;" :: "r"(dst), "l"(src));
}
__device__ __forceinline__ void ldsm4(uint32_t& r0, uint32_t& r1, uint32_t& r2, uint32_t& r3,
                                      uint32_t addr) {
    asm volatile("ldmatrix.sync.aligned.m8n8.x4.shared.b16 {%0,%1,%2,%3}, [%4];"
                 : "=r"(r0), "=r"(r1), "=r"(r2), "=r"(r3) : "r"(addr));
}
__device__ __forceinline__ void mma_s8(int* c, uint32_t a0, uint32_t a1, uint32_t a2, uint32_t a3,
                                       uint32_t b0, uint32_t b1) {
    asm volatile("mma.sync.aligned.m16n8k32.row.col.s32.s8.s8.s32 "
                 "{%0,%1,%2,%3}, {%4,%5,%6,%7}, {%8,%9}, {%0,%1,%2,%3};"
                 : "+r"(c[0]), "+r"(c[1]), "+r"(c[2]), "+r"(c[3])
                 : "r"(a0), "r"(a1), "r"(a2), "r"(a3), "r"(b0), "r"(b1));
}

// ---------------------------------------------------------------------------
// Pack passes
// ---------------------------------------------------------------------------
__global__ void pack_x_s8_kernel(const float* __restrict__ x) {
    int token = blockIdx.x * (blockDim.x >> 5) + (threadIdx.x >> 5);
    int lane  = threadIdx.x & 31;
    const float4* row = (const float4*)(x + (size_t)token * D_DIM);
    uint8_t* qrow = g_Xq + (size_t)token * D_DIM;
    float m = 0.f;
    #pragma unroll 8
    for (int c = 0; c < 32; ++c) {
        float4 v = row[c * 32 + lane];
        m = fmaxf(m, fmaxf(fmaxf(fabsf(v.x), fabsf(v.y)), fmaxf(fabsf(v.z), fabsf(v.w))));
        uint32_t b = (v.x < 0.f ? S8_N1 : S8_P1)
                   | ((v.y < 0.f ? S8_N1 : S8_P1) << 8)
                   | ((v.z < 0.f ? S8_N1 : S8_P1) << 16)
                   | ((v.w < 0.f ? S8_N1 : S8_P1) << 24);
        *(uint32_t*)(qrow + c * 128 + lane * 4) = b;
    }
    #pragma unroll
    for (int o = 16; o; o >>= 1) m = fmaxf(m, __shfl_xor_sync(0xffffffffu, m, o));
    if (lane == 0) g_bx[token] = m + F32_EPS;
}

__global__ __launch_bounds__(256)
void pack_k_s8_kernel(const float* __restrict__ kern) {
    __shared__ uint8_t T[128 * 132];
    __shared__ float smax[128];
    const int tid = threadIdx.x;
    const int f0 = blockIdx.x * 128, d0 = blockIdx.y * 128;
    if (tid < 128) smax[tid] = 0.f;
    __syncthreads();

    const int fq = tid & 31;
    float m0 = 0.f, m1 = 0.f, m2 = 0.f, m3 = 0.f;
    #pragma unroll 4
    for (int i = 0; i < 16; ++i) {
        int dr = i * 8 + (tid >> 5);
        float4 v = *(const float4*)(kern + (size_t)(d0 + dr) * F_DIM + f0 + fq * 4);
        m0 = fmaxf(m0, fabsf(v.x)); m1 = fmaxf(m1, fabsf(v.y));
        m2 = fmaxf(m2, fabsf(v.z)); m3 = fmaxf(m3, fabsf(v.w));
        T[(fq * 4 + 0) * 132 + dr] = v.x < 0.f ? S8_N1 : S8_P1;
        T[(fq * 4 + 1) * 132 + dr] = v.y < 0.f ? S8_N1 : S8_P1;
        T[(fq * 4 + 2) * 132 + dr] = v.z < 0.f ? S8_N1 : S8_P1;
        T[(fq * 4 + 3) * 132 + dr] = v.w < 0.f ? S8_N1 : S8_P1;
    }
    atomicMax((int*)&smax[fq * 4 + 0], __float_as_int(m0));
    atomicMax((int*)&smax[fq * 4 + 1], __float_as_int(m1));
    atomicMax((int*)&smax[fq * 4 + 2], __float_as_int(m2));
    atomicMax((int*)&smax[fq * 4 + 3], __float_as_int(m3));
    __syncthreads();

    #pragma unroll 4
    for (int i = 0; i < 16; ++i) {
        int idx = i * 256 + tid;
        int fr = idx >> 5, wq = idx & 31;
        uint32_t w = *(uint32_t*)&T[fr * 132 + wq * 4];
        *(uint32_t*)(g_Kq + (size_t)(f0 + fr) * D_DIM + d0 + wq * 4) = w;
    }
    if (tid < 128) g_bkpart[blockIdx.y][f0 + tid] = smax[tid];
}

// Derive packed sign bits from s8 arrays (bit = byte>>7).
// rows = M_TOK (X) or F_DIM (K); thread -> (row = bx*256+tid, chunk = by).
__global__ void bits_from_s8_kernel(const uint8_t* __restrict__ q, uint32_t* __restrict__ bits,
                                    int nrows) {
    int r = blockIdx.x * 256 + threadIdx.x;
    int c = blockIdx.y;
    const uint32_t* p = (const uint32_t*)(q + (size_t)r * D_DIM + c * 32);
    uint32_t w = 0;
    #pragma unroll
    for (int wi = 0; wi < 8; ++wi) {
        uint32_t v = p[wi];
        uint32_t nib = ((v >> 7) & 1u) | (((v >> 15) & 1u) << 1)
                     | (((v >> 23) & 1u) << 2) | (((v >> 31) & 1u) << 3);
        w |= nib << (wi * 4);
    }
    bits[(size_t)c * nrows + r] = w;
}

__global__ void reduce_bk_kernel() {
    int f = blockIdx.x * blockDim.x + threadIdx.x;
    float m = 0.f;
    #pragma unroll
    for (int s = 0; s < 32; ++s) m = fmaxf(m, g_bkpart[s][f]);
    g_bk[f] = m + F32_EPS;
}

// ---------------------------------------------------------------------------
// Warp-split hybrid GEMM: 512 threads per 128x128 tile.
//   warps 0-11 : popcount path, columns [0,96)   (ALU pipe)
//   warps 12-15: s8 mma.sync,   columns [96,128) (tensor pipe)
// Stage (24576 B): As8 16KB @0 | Bs8 4KB @16384 | Xbits 2KB @20480 | Kbits 1.5KB @22528
// ---------------------------------------------------------------------------
#define STG2 24576

__global__ __launch_bounds__(512, 2)
void hybrid_ws_gemm(const float* __restrict__ bias, float* __restrict__ out) {
    extern __shared__ uint8_t smem[];
    const uint32_t sb = smem_u32(smem);
    const int tid = threadIdx.x, wid = tid >> 5, lane = tid & 31;
    const int f0 = blockIdx.x * 128;
    const int t0 = blockIdx.y * 128;

    const uint8_t* __restrict__ gA  = g_Xq + (size_t)t0 * D_DIM;
    const uint8_t* __restrict__ gBq = g_Kq + (size_t)(f0 + 96) * D_DIM;

    // fill-role constants
    const int fa_r = tid >> 3, fa_c = (tid & 7) << 4;          // As8 (x2)
    const int fb_r = (tid & 255) >> 3, fb_c = (tid & 7) << 4;  // Bs8 (tid<256)
    const int fx_i = tid - 256, fx_ch = fx_i >> 5, fx_q = fx_i & 31;
    const int fk_i = tid - 384, fk_ch = fk_i / 24, fk_q = fk_i - fk_ch * 24;

    auto fill = [&](int kt, int st) {
        const uint32_t base = sb + st * STG2;
        cp16(base + sw128(fa_r * 128 + fa_c), gA + (size_t)fa_r * D_DIM + kt * 128 + fa_c);
        cp16(base + sw128((fa_r + 64) * 128 + fa_c),
             gA + (size_t)(fa_r + 64) * D_DIM + kt * 128 + fa_c);
        if (tid < 256) {
            cp16(base + 16384 + sw128(fb_r * 128 + fb_c),
                 gBq + (size_t)fb_r * D_DIM + kt * 128 + fb_c);
        } else if (tid < 384) {
            cp16(base + 20480 + fx_ch * 512 + fx_q * 16,
                 g_Xbits + (size_t)(kt * 4 + fx_ch) * M_TOK + t0 + fx_q * 4);
        } else if (tid < 480) {
            cp16(base + 22528 + fk_ch * 384 + fk_q * 16,
                 g_Kbits + (size_t)(kt * 4 + fk_ch) * F_DIM + f0 + fk_q * 4);
        }
        asm volatile("cp.async.commit_group;" ::: "memory");
    };

    fill(0, 0);

    if (wid < 12) {
        // ---------------- popcount path ----------------
        const int pm = wid & 3, pn = wid >> 2;       // 4 x 3 warp grid
        const int r0 = pm * 32 + (lane >> 3) * 8;    // 8 rows
        const int c0 = pn * 32 + (lane & 7) * 4;     // 4 cols
        int acc[8][4];
        #pragma unroll
        for (int i = 0; i < 8; ++i)
            #pragma unroll
            for (int j = 0; j < 4; ++j) acc[i][j] = 0;

        for (int kt = 0; kt < 32; ++kt) {
            if (kt < 31) {
                fill(kt + 1, (kt + 1) & 1);
                asm volatile("cp.async.wait_group 1;" ::: "memory");
            } else {
                asm volatile("cp.async.wait_group 0;" ::: "memory");
            }
            __syncthreads();
            const uint8_t* base = smem + (kt & 1) * STG2;
            #pragma unroll
            for (int c = 0; c < 4; ++c) {
                uint32_t xa[8], kb[4];
                *(uint4*)&xa[0] = *(const uint4*)(base + 20480 + c * 512 + r0 * 4);
                *(uint4*)&xa[4] = *(const uint4*)(base + 20480 + c * 512 + r0 * 4 + 16);
                *(uint4*)&kb[0] = *(const uint4*)(base + 22528 + c * 384 + c0 * 4);
                #pragma unroll
                for (int i = 0; i < 8; ++i)
                    #pragma unroll
                    for (int j = 0; j < 4; ++j)
                        acc[i][j] += __popc(xa[i] ^ kb[j]);
            }
            __syncthreads();
        }

        const int trow = t0 + r0, tcol = f0 + c0;
        float bk4[4], bs4[4];
        #pragma unroll
        for (int j = 0; j < 4; ++j) { bk4[j] = g_bk[tcol + j]; bs4[j] = bias[tcol + j]; }
        #pragma unroll
        for (int i = 0; i < 8; ++i) {
            float sx = 0.25f * g_bx[trow + i];
            float4 r;
            r.x = fmaf(sx * bk4[0], (float)(D_DIM - 2 * acc[i][0]), bs4[0]);
            r.y = fmaf(sx * bk4[1], (float)(D_DIM - 2 * acc[i][1]), bs4[1]);
            r.z = fmaf(sx * bk4[2], (float)(D_DIM - 2 * acc[i][2]), bs4[2]);
            r.w = fmaf(sx * bk4[3], (float)(D_DIM - 2 * acc[i][3]), bs4[3]);
            *(float4*)(out + (size_t)(trow + i) * F_DIM + tcol) = r;
        }
    } else {
        // ---------------- s8 mma path (cols 96..127) ----------------
        const int iw = wid - 12;
        const int wm = iw & 1, wn = iw >> 1;         // 2 x 2, warp tile 64m x 16n
        int acc[4][2][4];
        #pragma unroll
        for (int mi = 0; mi < 4; ++mi)
            #pragma unroll
            for (int ni = 0; ni < 2; ++ni)
                #pragma unroll
                for (int r = 0; r < 4; ++r) acc[mi][ni][r] = 0;

        const int arow = wm * 64 + (lane & 15);
        const int brow = wn * 16 + (lane & 15);
        const int khalf = (lane & 16);

        for (int kt = 0; kt < 32; ++kt) {
            if (kt < 31) {
                fill(kt + 1, (kt + 1) & 1);
                asm volatile("cp.async.wait_group 1;" ::: "memory");
            } else {
                asm volatile("cp.async.wait_group 0;" ::: "memory");
            }
            __syncthreads();
            const uint32_t aSt = sb + (kt & 1) * STG2;
            const uint32_t bSt = aSt + 16384;
            #pragma unroll
            for (int ks = 0; ks < 4; ++ks) {
                const int kcol = ks * 32 + khalf;
                uint32_t b0, b1, b2, b3;
                ldsm4(b0, b1, b2, b3, bSt + sw128(brow * 128 + kcol));
                #pragma unroll
                for (int mi = 0; mi < 4; ++mi) {
                    uint32_t a0, a1, a2, a3;
                    ldsm4(a0, a1, a2, a3, aSt + sw128((arow + mi * 16) * 128 + kcol));
                    mma_s8(acc[mi][0], a0, a1, a2, a3, b0, b2);
                    mma_s8(acc[mi][1], a0, a1, a2, a3, b1, b3);
                }
            }
            __syncthreads();
        }

        const int lrow = lane >> 2;
        const int lcol = (lane & 3) * 2;
        const int rbase = t0 + wm * 64;
        const int cbase = f0 + 96 + wn * 16;
        #pragma unroll
        for (int mi = 0; mi < 4; ++mi) {
            float sx0 = 0.25f * g_bx[rbase + mi * 16 + lrow];
            float sx1 = 0.25f * g_bx[rbase + mi * 16 + lrow + 8];
            #pragma unroll
            for (int ni = 0; ni < 2; ++ni) {
                int c = cbase + ni * 8 + lcol;
                float k0v = g_bk[c], k1v = g_bk[c + 1];
                float b0v = bias[c], b1v = bias[c + 1];
                float2 v0, v1;
                v0.x = fmaf(sx0 * k0v, (float)acc[mi][ni][0], b0v);
                v0.y = fmaf(sx0 * k1v, (float)acc[mi][ni][1], b1v);
                v1.x = fmaf(sx1 * k0v, (float)acc[mi][ni][2], b0v);
                v1.y = fmaf(sx1 * k1v, (float)acc[mi][ni][3], b1v);
                *(float2*)(out + (size_t)(rbase + mi * 16 + lrow) * F_DIM + c) = v0;
                *(float2*)(out + (size_t)(rbase + mi * 16 + lrow + 8) * F_DIM + c) = v1;
            }
        }
    }
}

// ---------------------------------------------------------------------------
extern "C" void kernel_launch(void* const* d_in, const int* in_sizes, int n_in,
                              void* d_out, int out_size) {
    const float* x    = (const float*)d_in[0];
    const float* kern = (const float*)d_in[1];
    const float* bias = (const float*)d_in[2];
    float* out = (float*)d_out;

    pack_x_s8_kernel<<<M_TOK / 8, 256>>>(x);
    dim3 gk(F_DIM / 128, D_DIM / 128);
    pack_k_s8_kernel<<<gk, 256>>>(kern);

    // get base pointers of __device__ globals for bits kernels
    uint8_t *dXq, *dKq; uint32_t *dXb, *dKb;
    cudaGetSymbolAddress((void**)&dXq, g_Xq);
    cudaGetSymbolAddress((void**)&dKq, g_Kq);
    cudaGetSymbolAddress((void**)&dXb, g_Xbits);
    cudaGetSymbolAddress((void**)&dKb, g_Kbits);

    dim3 gxb(M_TOK / 256, NCHUNK);
    bits_from_s8_kernel<<<gxb, 256>>>(dXq, dXb, M_TOK);
    dim3 gkb(F_DIM / 256, NCHUNK);
    bits_from_s8_kernel<<<gkb, 256>>>(dKq, dKb, F_DIM);

    reduce_bk_kernel<<<F_DIM / 256, 256>>>();

    cudaFuncSetAttribute(hybrid_ws_gemm,
                         cudaFuncAttributeMaxDynamicSharedMemorySize, 2 * STG2);
    dim3 gg(F_DIM / 128, M_TOK / 128);
    hybrid_ws_gemm<<<gg, 512, 2 * STG2>>>(bias, out);
}

// round 6
// speedup vs baseline: 2.4667x; 1.0254x over previous
#include <cuda_runtime.h>
#include <cstdint>

// x (4,2048,4096) f32, kernel (4096,16384) f32, bias (16384) f32 -> out (4,2048,16384) f32
#define M_TOK   8192
#define D_DIM   4096
#define F_DIM   16384
#define NCHUNK  128
#define F32_EPS 1.1920929e-07f

#define S8_P1 0x01u
#define S8_N1 0xFFu

// ---------------- static device scratch ----------------
__device__ __align__(16) uint8_t  g_Xq[(size_t)M_TOK * D_DIM];   // s8 ±1 [token][d]
__device__ __align__(16) uint8_t  g_Kq[(size_t)F_DIM * D_DIM];   // s8 ±1 [feat][d]
__device__ __align__(16) uint32_t g_Xbits[NCHUNK * M_TOK];       // [chunk][token]
__device__ __align__(16) uint32_t g_Kbits[NCHUNK * F_DIM];       // [chunk][feature]
__device__ float g_bx[M_TOK];
__device__ float g_bk[F_DIM];
__device__ float g_bkpart[32][F_DIM];

__device__ __forceinline__ uint32_t smem_u32(const void* p) {
    uint32_t a;
    asm("{ .reg .u64 t; cvta.to.shared.u64 t, %1; cvt.u32.u64 %0, t; }" : "=r"(a) : "l"(p));
    return a;
}
__device__ __forceinline__ uint32_t sw128(uint32_t off) { return off ^ ((off >> 3) & 0x70u); }
__device__ __forceinline__ void cp16(uint32_t dst, const void* src) {
    asm volatile("cp.async.cg.shared.global [%0], [%1], 16;" :: "r"(dst), "l"(src));
}
__device__ __forceinline__ void ldsm4(uint32_t& r0, uint32_t& r1, uint32_t& r2, uint32_t& r3,
                                      uint32_t addr) {
    asm volatile("ldmatrix.sync.aligned.m8n8.x4.shared.b16 {%0,%1,%2,%3}, [%4];"
                 : "=r"(r0), "=r"(r1), "=r"(r2), "=r"(r3) : "r"(addr));
}
__device__ __forceinline__ void mma_s8(int* c, uint32_t a0, uint32_t a1, uint32_t a2, uint32_t a3,
                                       uint32_t b0, uint32_t b1) {
    asm volatile("mma.sync.aligned.m16n8k32.row.col.s32.s8.s8.s32 "
                 "{%0,%1,%2,%3}, {%4,%5,%6,%7}, {%8,%9}, {%0,%1,%2,%3};"
                 : "+r"(c[0]), "+r"(c[1]), "+r"(c[2]), "+r"(c[3])
                 : "r"(a0), "r"(a1), "r"(a2), "r"(a3), "r"(b0), "r"(b1));
}

// ---------------------------------------------------------------------------
// Pass A: per-token max|x| + s8 pack + fused bit pack (nibble + butterfly OR).
// One warp per token.
// ---------------------------------------------------------------------------
__global__ void pack_x_s8_kernel(const float* __restrict__ x) {
    int token = blockIdx.x * (blockDim.x >> 5) + (threadIdx.x >> 5);
    int lane  = threadIdx.x & 31;
    const float4* row = (const float4*)(x + (size_t)token * D_DIM);
    uint8_t* qrow = g_Xq + (size_t)token * D_DIM;
    const int sh = (lane & 7) * 4;
    float m = 0.f;
    #pragma unroll 4
    for (int c = 0; c < 32; ++c) {
        float4 v = row[c * 32 + lane];
        m = fmaxf(m, fmaxf(fmaxf(fabsf(v.x), fabsf(v.y)), fmaxf(fabsf(v.z), fabsf(v.w))));
        uint32_t b = (v.x < 0.f ? S8_N1 : S8_P1)
                   | ((v.y < 0.f ? S8_N1 : S8_P1) << 8)
                   | ((v.z < 0.f ? S8_N1 : S8_P1) << 16)
                   | ((v.w < 0.f ? S8_N1 : S8_P1) << 24);
        *(uint32_t*)(qrow + c * 128 + lane * 4) = b;
        // fused bit pack: nibble of 4 signs -> 32-bit chunk via OR-butterfly
        uint32_t nib = (v.x < 0.f ? 1u : 0u) | (v.y < 0.f ? 2u : 0u)
                     | (v.z < 0.f ? 4u : 0u) | (v.w < 0.f ? 8u : 0u);
        uint32_t w = nib << sh;
        w |= __shfl_xor_sync(0xffffffffu, w, 1);
        w |= __shfl_xor_sync(0xffffffffu, w, 2);
        w |= __shfl_xor_sync(0xffffffffu, w, 4);
        if ((lane & 7) == 0)
            g_Xbits[(c * 4 + (lane >> 3)) * M_TOK + token] = w;
    }
    #pragma unroll
    for (int o = 16; o; o >>= 1) m = fmaxf(m, __shfl_xor_sync(0xffffffffu, m, o));
    if (lane == 0) g_bx[token] = m + F32_EPS;
}

// ---------------------------------------------------------------------------
// Pass B: transpose K (d,f)->(f,d) s8 pack + per-feature partial max +
// fused bit pack in the write-out loop (each warp owns one f-row).
// ---------------------------------------------------------------------------
__global__ __launch_bounds__(256)
void pack_k_s8_kernel(const float* __restrict__ kern) {
    __shared__ uint8_t T[128 * 132];
    __shared__ float smax[128];
    const int tid = threadIdx.x;
    const int f0 = blockIdx.x * 128, d0 = blockIdx.y * 128;
    if (tid < 128) smax[tid] = 0.f;
    __syncthreads();

    const int fq = tid & 31;
    float m0 = 0.f, m1 = 0.f, m2 = 0.f, m3 = 0.f;
    #pragma unroll 4
    for (int i = 0; i < 16; ++i) {
        int dr = i * 8 + (tid >> 5);
        float4 v = *(const float4*)(kern + (size_t)(d0 + dr) * F_DIM + f0 + fq * 4);
        m0 = fmaxf(m0, fabsf(v.x)); m1 = fmaxf(m1, fabsf(v.y));
        m2 = fmaxf(m2, fabsf(v.z)); m3 = fmaxf(m3, fabsf(v.w));
        T[(fq * 4 + 0) * 132 + dr] = v.x < 0.f ? S8_N1 : S8_P1;
        T[(fq * 4 + 1) * 132 + dr] = v.y < 0.f ? S8_N1 : S8_P1;
        T[(fq * 4 + 2) * 132 + dr] = v.z < 0.f ? S8_N1 : S8_P1;
        T[(fq * 4 + 3) * 132 + dr] = v.w < 0.f ? S8_N1 : S8_P1;
    }
    atomicMax((int*)&smax[fq * 4 + 0], __float_as_int(m0));
    atomicMax((int*)&smax[fq * 4 + 1], __float_as_int(m1));
    atomicMax((int*)&smax[fq * 4 + 2], __float_as_int(m2));
    atomicMax((int*)&smax[fq * 4 + 3], __float_as_int(m3));
    __syncthreads();

    const int lane = tid & 31;
    const int sh = (lane & 7) * 4;
    const int cbase = (d0 >> 5) + (lane >> 3);
    #pragma unroll 4
    for (int i = 0; i < 16; ++i) {
        int idx = i * 256 + tid;
        int fr = idx >> 5;              // warp-uniform row
        uint32_t w = *(uint32_t*)&T[fr * 132 + lane * 4];
        *(uint32_t*)(g_Kq + (size_t)(f0 + fr) * D_DIM + d0 + lane * 4) = w;
        uint32_t nib = ((w >> 7) & 1u) | ((w >> 14) & 2u)
                     | ((w >> 21) & 4u) | ((w >> 28) & 8u);
        uint32_t bw = nib << sh;
        bw |= __shfl_xor_sync(0xffffffffu, bw, 1);
        bw |= __shfl_xor_sync(0xffffffffu, bw, 2);
        bw |= __shfl_xor_sync(0xffffffffu, bw, 4);
        if ((lane & 7) == 0)
            g_Kbits[(size_t)cbase * F_DIM + f0 + fr] = bw;
    }
    if (tid < 128) g_bkpart[blockIdx.y][f0 + tid] = smax[tid];
}

__global__ void reduce_bk_kernel() {
    int f = blockIdx.x * blockDim.x + threadIdx.x;
    float m = 0.f;
    #pragma unroll
    for (int s = 0; s < 32; ++s) m = fmaxf(m, g_bkpart[s][f]);
    g_bk[f] = m + F32_EPS;
}

// ---------------------------------------------------------------------------
// Warp-split hybrid GEMM, 256-byte k-step (16 iters), double-buffered.
//   warps 0-11 : XOR+POPC, columns [0,96)   (ALU pipe)
//   warps 12-15: s8 mma.sync, columns [96,128) (tensor pipe)
// Stage (48KB): As8 2x16KB @0 | Bs8 2x4KB @32768 | Xbits 4KB @40960 | Kbits 3KB @45056
// ---------------------------------------------------------------------------
#define STG3   49152
#define OFF_B  32768
#define OFF_X  40960
#define OFF_K  45056

__global__ __launch_bounds__(512, 2)
void hybrid_ws_gemm(const float* __restrict__ bias, float* __restrict__ out) {
    extern __shared__ uint8_t smem[];
    const uint32_t sb = smem_u32(smem);
    const int tid = threadIdx.x, wid = tid >> 5, lane = tid & 31;
    const int f0 = blockIdx.x * 128;
    const int t0 = blockIdx.y * 128;

    const uint8_t* __restrict__ gA  = g_Xq + (size_t)t0 * D_DIM;
    const uint8_t* __restrict__ gBq = g_Kq + (size_t)(f0 + 96) * D_DIM;

    auto fill = [&](int kt, int st) {
        const uint32_t base = sb + st * STG3;
        const size_t gk = (size_t)kt * 256;
        #pragma unroll
        for (int t = 0; t < 4; ++t) {
            int idx = t * 512 + tid;
            int sub = idx >> 10, r = (idx >> 3) & 127, c = (idx & 7) << 4;
            cp16(base + sub * 16384 + sw128(r * 128 + c),
                 gA + (size_t)r * D_DIM + gk + sub * 128 + c);
        }
        {
            int sub = tid >> 8, r = (tid >> 3) & 31, c = (tid & 7) << 4;
            cp16(base + OFF_B + sub * 4096 + sw128(r * 128 + c),
                 gBq + (size_t)r * D_DIM + gk + sub * 128 + c);
        }
        if (tid < 256) {
            int ch = tid >> 5, q = tid & 31;
            cp16(base + OFF_X + ch * 512 + q * 16,
                 g_Xbits + (size_t)(kt * 8 + ch) * M_TOK + t0 + q * 4);
        } else if (tid < 448) {
            int i = tid - 256, ch = i / 24, q = i - ch * 24;
            cp16(base + OFF_K + ch * 384 + q * 16,
                 g_Kbits + (size_t)(kt * 8 + ch) * F_DIM + f0 + q * 4);
        }
        asm volatile("cp.async.commit_group;" ::: "memory");
    };

    fill(0, 0);

    if (wid < 12) {
        // ---------------- popcount path (cols 0..95) ----------------
        const int pm = wid & 3, pn = wid >> 2;       // 4m x 3n warp grid
        const int r0 = pm * 32 + (lane >> 3) * 8;
        const int c0 = pn * 32 + (lane & 7) * 4;
        int acc[8][4];
        #pragma unroll
        for (int i = 0; i < 8; ++i)
            #pragma unroll
            for (int j = 0; j < 4; ++j) acc[i][j] = 0;

        for (int kt = 0; kt < 16; ++kt) {
            if (kt < 15) {
                fill(kt + 1, (kt + 1) & 1);
                asm volatile("cp.async.wait_group 1;" ::: "memory");
            } else {
                asm volatile("cp.async.wait_group 0;" ::: "memory");
            }
            __syncthreads();
            const uint8_t* base = smem + (kt & 1) * STG3;
            #pragma unroll
            for (int c = 0; c < 8; ++c) {
                uint32_t xa[8], kb[4];
                *(uint4*)&xa[0] = *(const uint4*)(base + OFF_X + c * 512 + r0 * 4);
                *(uint4*)&xa[4] = *(const uint4*)(base + OFF_X + c * 512 + r0 * 4 + 16);
                *(uint4*)&kb[0] = *(const uint4*)(base + OFF_K + c * 384 + c0 * 4);
                #pragma unroll
                for (int i = 0; i < 8; ++i)
                    #pragma unroll
                    for (int j = 0; j < 4; ++j)
                        acc[i][j] += __popc(xa[i] ^ kb[j]);
            }
            __syncthreads();
        }

        const int trow = t0 + r0, tcol = f0 + c0;
        float bk4[4], bs4[4];
        #pragma unroll
        for (int j = 0; j < 4; ++j) { bk4[j] = g_bk[tcol + j]; bs4[j] = bias[tcol + j]; }
        #pragma unroll
        for (int i = 0; i < 8; ++i) {
            float sx = 0.25f * g_bx[trow + i];
            float4 r;
            r.x = fmaf(sx * bk4[0], (float)(D_DIM - 2 * acc[i][0]), bs4[0]);
            r.y = fmaf(sx * bk4[1], (float)(D_DIM - 2 * acc[i][1]), bs4[1]);
            r.z = fmaf(sx * bk4[2], (float)(D_DIM - 2 * acc[i][2]), bs4[2]);
            r.w = fmaf(sx * bk4[3], (float)(D_DIM - 2 * acc[i][3]), bs4[3]);
            *(float4*)(out + (size_t)(trow + i) * F_DIM + tcol) = r;
        }
    } else {
        // ---------------- s8 mma path (cols 96..127) ----------------
        const int iw = wid - 12;
        const int wm = iw & 1, wn = iw >> 1;         // 2m x 2n, warp tile 64x16
        int acc[4][2][4];
        #pragma unroll
        for (int mi = 0; mi < 4; ++mi)
            #pragma unroll
            for (int ni = 0; ni < 2; ++ni)
                #pragma unroll
                for (int r = 0; r < 4; ++r) acc[mi][ni][r] = 0;

        const int arow = wm * 64 + (lane & 15);
        const int brow = wn * 16 + (lane & 15);
        const int khalf = (lane & 16);

        for (int kt = 0; kt < 16; ++kt) {
            if (kt < 15) {
                fill(kt + 1, (kt + 1) & 1);
                asm volatile("cp.async.wait_group 1;" ::: "memory");
            } else {
                asm volatile("cp.async.wait_group 0;" ::: "memory");
            }
            __syncthreads();
            const uint32_t stb = sb + (kt & 1) * STG3;
            #pragma unroll
            for (int ks = 0; ks < 8; ++ks) {
                const int sub = ks >> 2;
                const int kcol = (ks & 3) * 32 + khalf;
                const uint32_t aSt = stb + sub * 16384;
                const uint32_t bSt = stb + OFF_B + sub * 4096;
                uint32_t b0, b1, b2, b3;
                ldsm4(b0, b1, b2, b3, bSt + sw128(brow * 128 + kcol));
                #pragma unroll
                for (int mi = 0; mi < 4; ++mi) {
                    uint32_t a0, a1, a2, a3;
                    ldsm4(a0, a1, a2, a3, aSt + sw128((arow + mi * 16) * 128 + kcol));
                    mma_s8(acc[mi][0], a0, a1, a2, a3, b0, b2);
                    mma_s8(acc[mi][1], a0, a1, a2, a3, b1, b3);
                }
            }
            __syncthreads();
        }

        const int lrow = lane >> 2;
        const int lcol = (lane & 3) * 2;
        const int rbase = t0 + wm * 64;
        const int cbase = f0 + 96 + wn * 16;
        #pragma unroll
        for (int mi = 0; mi < 4; ++mi) {
            float sx0 = 0.25f * g_bx[rbase + mi * 16 + lrow];
            float sx1 = 0.25f * g_bx[rbase + mi * 16 + lrow + 8];
            #pragma unroll
            for (int ni = 0; ni < 2; ++ni) {
                int c = cbase + ni * 8 + lcol;
                float k0v = g_bk[c], k1v = g_bk[c + 1];
                float b0v = bias[c], b1v = bias[c + 1];
                float2 v0, v1;
                v0.x = fmaf(sx0 * k0v, (float)acc[mi][ni][0], b0v);
                v0.y = fmaf(sx0 * k1v, (float)acc[mi][ni][1], b1v);
                v1.x = fmaf(sx1 * k0v, (float)acc[mi][ni][2], b0v);
                v1.y = fmaf(sx1 * k1v, (float)acc[mi][ni][3], b1v);
                *(float2*)(out + (size_t)(rbase + mi * 16 + lrow) * F_DIM + c) = v0;
                *(float2*)(out + (size_t)(rbase + mi * 16 + lrow + 8) * F_DIM + c) = v1;
            }
        }
    }
}

// ---------------------------------------------------------------------------
extern "C" void kernel_launch(void* const* d_in, const int* in_sizes, int n_in,
                              void* d_out, int out_size) {
    const float* x    = (const float*)d_in[0];
    const float* kern = (const float*)d_in[1];
    const float* bias = (const float*)d_in[2];
    float* out = (float*)d_out;

    pack_x_s8_kernel<<<M_TOK / 8, 256>>>(x);
    dim3 gk(F_DIM / 128, D_DIM / 128);
    pack_k_s8_kernel<<<gk, 256>>>(kern);
    reduce_bk_kernel<<<F_DIM / 256, 256>>>();

    cudaFuncSetAttribute(hybrid_ws_gemm,
                         cudaFuncAttributeMaxDynamicSharedMemorySize, 2 * STG3);
    dim3 gg(F_DIM / 128, M_TOK / 128);
    hybrid_ws_gemm<<<gg, 512, 2 * STG3>>>(bias, out);
}

// round 7
// speedup vs baseline: 2.5538x; 1.0353x over previous
#include <cuda_runtime.h>
#include <cstdint>

// x (4,2048,4096) f32, kernel (4096,16384) f32, bias (16384) f32 -> out (4,2048,16384) f32
#define M_TOK   8192
#define D_DIM   4096
#define F_DIM   16384
#define NCHUNK  128
#define F32_EPS 1.1920929e-07f

#define S8_P1 0x01u
#define S8_N1 0xFFu

// ---------------- static device scratch ----------------
__device__ __align__(16) uint8_t  g_Xq[(size_t)M_TOK * D_DIM];   // s8 ±1 [token][d]
__device__ __align__(16) uint8_t  g_Kq[(size_t)F_DIM * D_DIM];   // s8 ±1 [feat][d]
__device__ __align__(16) uint32_t g_Xbits[NCHUNK * M_TOK];       // [chunk][token]
__device__ __align__(16) uint32_t g_Kbits[NCHUNK * F_DIM];       // [chunk][feature]
__device__ float g_bx[M_TOK];
__device__ float g_bk[F_DIM];
__device__ float g_bkpart[32][F_DIM];

__device__ __forceinline__ uint32_t smem_u32(const void* p) {
    uint32_t a;
    asm("{ .reg .u64 t; cvta.to.shared.u64 t, %1; cvt.u32.u64 %0, t; }" : "=r"(a) : "l"(p));
    return a;
}
__device__ __forceinline__ uint32_t sw128(uint32_t off) { return off ^ ((off >> 3) & 0x70u); }
__device__ __forceinline__ void cp16(uint32_t dst, const void* src) {
    asm volatile("cp.async.cg.shared.global [%0], [%1], 16;" :: "r"(dst), "l"(src));
}
__device__ __forceinline__ void ldsm4(uint32_t& r0, uint32_t& r1, uint32_t& r2, uint32_t& r3,
                                      uint32_t addr) {
    asm volatile("ldmatrix.sync.aligned.m8n8.x4.shared.b16 {%0,%1,%2,%3}, [%4];"
                 : "=r"(r0), "=r"(r1), "=r"(r2), "=r"(r3) : "r"(addr));
}
__device__ __forceinline__ void mma_s8(int* c, uint32_t a0, uint32_t a1, uint32_t a2, uint32_t a3,
                                       uint32_t b0, uint32_t b1) {
    asm volatile("mma.sync.aligned.m16n8k32.row.col.s32.s8.s8.s32 "
                 "{%0,%1,%2,%3}, {%4,%5,%6,%7}, {%8,%9}, {%0,%1,%2,%3};"
                 : "+r"(c[0]), "+r"(c[1]), "+r"(c[2]), "+r"(c[3])
                 : "r"(a0), "r"(a1), "r"(a2), "r"(a3), "r"(b0), "r"(b1));
}
#define CP_COMMIT() asm volatile("cp.async.commit_group;" ::: "memory")
#define BAR_POPC()  asm volatile("bar.sync 1, 384;" ::: "memory")
#define BAR_IMMA()  asm volatile("bar.sync 2, 128;" ::: "memory")

// ---------------------------------------------------------------------------
// Pass A: per-token max|x| + s8 pack + fused bit pack (validated in R6).
// ---------------------------------------------------------------------------
__global__ void pack_x_s8_kernel(const float* __restrict__ x) {
    int token = blockIdx.x * (blockDim.x >> 5) + (threadIdx.x >> 5);
    int lane  = threadIdx.x & 31;
    const float4* row = (const float4*)(x + (size_t)token * D_DIM);
    uint8_t* qrow = g_Xq + (size_t)token * D_DIM;
    const int sh = (lane & 7) * 4;
    float m = 0.f;
    #pragma unroll 4
    for (int c = 0; c < 32; ++c) {
        float4 v = row[c * 32 + lane];
        m = fmaxf(m, fmaxf(fmaxf(fabsf(v.x), fabsf(v.y)), fmaxf(fabsf(v.z), fabsf(v.w))));
        uint32_t b = (v.x < 0.f ? S8_N1 : S8_P1)
                   | ((v.y < 0.f ? S8_N1 : S8_P1) << 8)
                   | ((v.z < 0.f ? S8_N1 : S8_P1) << 16)
                   | ((v.w < 0.f ? S8_N1 : S8_P1) << 24);
        *(uint32_t*)(qrow + c * 128 + lane * 4) = b;
        uint32_t nib = (v.x < 0.f ? 1u : 0u) | (v.y < 0.f ? 2u : 0u)
                     | (v.z < 0.f ? 4u : 0u) | (v.w < 0.f ? 8u : 0u);
        uint32_t w = nib << sh;
        w |= __shfl_xor_sync(0xffffffffu, w, 1);
        w |= __shfl_xor_sync(0xffffffffu, w, 2);
        w |= __shfl_xor_sync(0xffffffffu, w, 4);
        if ((lane & 7) == 0)
            g_Xbits[(c * 4 + (lane >> 3)) * M_TOK + token] = w;
    }
    #pragma unroll
    for (int o = 16; o; o >>= 1) m = fmaxf(m, __shfl_xor_sync(0xffffffffu, m, o));
    if (lane == 0) g_bx[token] = m + F32_EPS;
}

// ---------------------------------------------------------------------------
// Pass B: K transpose + s8 pack + fused bit pack + partial max (validated).
// ---------------------------------------------------------------------------
__global__ __launch_bounds__(256)
void pack_k_s8_kernel(const float* __restrict__ kern) {
    __shared__ uint8_t T[128 * 132];
    __shared__ float smax[128];
    const int tid = threadIdx.x;
    const int f0 = blockIdx.x * 128, d0 = blockIdx.y * 128;
    if (tid < 128) smax[tid] = 0.f;
    __syncthreads();

    const int fq = tid & 31;
    float m0 = 0.f, m1 = 0.f, m2 = 0.f, m3 = 0.f;
    #pragma unroll 4
    for (int i = 0; i < 16; ++i) {
        int dr = i * 8 + (tid >> 5);
        float4 v = *(const float4*)(kern + (size_t)(d0 + dr) * F_DIM + f0 + fq * 4);
        m0 = fmaxf(m0, fabsf(v.x)); m1 = fmaxf(m1, fabsf(v.y));
        m2 = fmaxf(m2, fabsf(v.z)); m3 = fmaxf(m3, fabsf(v.w));
        T[(fq * 4 + 0) * 132 + dr] = v.x < 0.f ? S8_N1 : S8_P1;
        T[(fq * 4 + 1) * 132 + dr] = v.y < 0.f ? S8_N1 : S8_P1;
        T[(fq * 4 + 2) * 132 + dr] = v.z < 0.f ? S8_N1 : S8_P1;
        T[(fq * 4 + 3) * 132 + dr] = v.w < 0.f ? S8_N1 : S8_P1;
    }
    atomicMax((int*)&smax[fq * 4 + 0], __float_as_int(m0));
    atomicMax((int*)&smax[fq * 4 + 1], __float_as_int(m1));
    atomicMax((int*)&smax[fq * 4 + 2], __float_as_int(m2));
    atomicMax((int*)&smax[fq * 4 + 3], __float_as_int(m3));
    __syncthreads();

    const int lane = tid & 31;
    const int sh = (lane & 7) * 4;
    const int cbase = (d0 >> 5) + (lane >> 3);
    #pragma unroll 4
    for (int i = 0; i < 16; ++i) {
        int idx = i * 256 + tid;
        int fr = idx >> 5;
        uint32_t w = *(uint32_t*)&T[fr * 132 + lane * 4];
        *(uint32_t*)(g_Kq + (size_t)(f0 + fr) * D_DIM + d0 + lane * 4) = w;
        uint32_t nib = ((w >> 7) & 1u) | ((w >> 14) & 2u)
                     | ((w >> 21) & 4u) | ((w >> 28) & 8u);
        uint32_t bw = nib << sh;
        bw |= __shfl_xor_sync(0xffffffffu, bw, 1);
        bw |= __shfl_xor_sync(0xffffffffu, bw, 2);
        bw |= __shfl_xor_sync(0xffffffffu, bw, 4);
        if ((lane & 7) == 0)
            g_Kbits[(size_t)cbase * F_DIM + f0 + fr] = bw;
    }
    if (tid < 128) g_bkpart[blockIdx.y][f0 + tid] = smax[tid];
}

__global__ void reduce_bk_kernel() {
    int f = blockIdx.x * blockDim.x + threadIdx.x;
    float m = 0.f;
    #pragma unroll
    for (int s = 0; s < 32; ++s) m = fmaxf(m, g_bkpart[s][f]);
    g_bk[f] = m + F32_EPS;
}

// ---------------------------------------------------------------------------
// Decoupled warp-split hybrid GEMM. 512 threads per 128x128 tile, k-step 256B.
//   warps 0-11 (384t): XOR+POPC cols [0,96), own 4-stage pipeline, bar.sync 1
//   warps 12-15(128t): s8 mma    cols [96,128), own 2-stage pipeline, bar.sync 2
// Smem: imma stages 2 x 40960 (A 32KB + B 8KB) at 0;
//       popc stages 4 x 7168  (X 4KB + K 3KB)  at 81920. Total 110592.
// ---------------------------------------------------------------------------
#define STG_I   40960
#define OFF_B   32768
#define POPC_0  81920
#define STG_P   7168
#define SMEM_SZ 110592

__global__ __launch_bounds__(512, 2)
void hybrid_dc_gemm(const float* __restrict__ bias, float* __restrict__ out) {
    extern __shared__ uint8_t smem[];
    const uint32_t sb = smem_u32(smem);
    const int tid = threadIdx.x, wid = tid >> 5, lane = tid & 31;
    const int f0 = blockIdx.x * 128;
    const int t0 = blockIdx.y * 128;

    if (wid < 12) {
        // ================= popcount group (cols 0..95) =================
        auto fillP = [&](int kt, int st) {
            const uint32_t base = sb + POPC_0 + st * STG_P;
            if (tid < 256) {
                int ch = tid >> 5, q = tid & 31;
                cp16(base + ch * 512 + q * 16,
                     g_Xbits + (size_t)(kt * 8 + ch) * M_TOK + t0 + q * 4);
            } else {
                int j = tid - 256;                       // 0..127
                cp16(base + 4096 + (j / 24) * 384 + (j % 24) * 16,
                     g_Kbits + (size_t)(kt * 8 + j / 24) * F_DIM + f0 + (j % 24) * 4);
            }
            if (tid < 64) {
                int j = 128 + tid;                       // 128..191
                cp16(base + 4096 + (j / 24) * 384 + (j % 24) * 16,
                     g_Kbits + (size_t)(kt * 8 + j / 24) * F_DIM + f0 + (j % 24) * 4);
            }
            CP_COMMIT();
        };

        const int pm = wid & 3, pn = wid >> 2;       // 4m x 3n warp grid
        const int r0 = pm * 32 + (lane >> 3) * 8;
        const int c0 = pn * 32 + (lane & 7) * 4;
        int acc[8][4];
        #pragma unroll
        for (int i = 0; i < 8; ++i)
            #pragma unroll
            for (int j = 0; j < 4; ++j) acc[i][j] = 0;

        fillP(0, 0);
        fillP(1, 1);
        for (int kt = 0; kt < 16; ++kt) {
            if (kt + 2 < 16) fillP(kt + 2, (kt + 2) & 3); else CP_COMMIT();
            asm volatile("cp.async.wait_group 2;" ::: "memory");
            BAR_POPC();
            const uint8_t* base = smem + POPC_0 + (kt & 3) * STG_P;
            #pragma unroll
            for (int c = 0; c < 8; ++c) {
                uint32_t xa[8], kb[4];
                *(uint4*)&xa[0] = *(const uint4*)(base + c * 512 + r0 * 4);
                *(uint4*)&xa[4] = *(const uint4*)(base + c * 512 + r0 * 4 + 16);
                *(uint4*)&kb[0] = *(const uint4*)(base + 4096 + c * 384 + c0 * 4);
                #pragma unroll
                for (int i = 0; i < 8; ++i)
                    #pragma unroll
                    for (int j = 0; j < 4; ++j)
                        acc[i][j] += __popc(xa[i] ^ kb[j]);
            }
        }

        const int trow = t0 + r0, tcol = f0 + c0;
        float bk4[4], bs4[4];
        #pragma unroll
        for (int j = 0; j < 4; ++j) { bk4[j] = g_bk[tcol + j]; bs4[j] = bias[tcol + j]; }
        #pragma unroll
        for (int i = 0; i < 8; ++i) {
            float sx = 0.25f * g_bx[trow + i];
            float4 r;
            r.x = fmaf(sx * bk4[0], (float)(D_DIM - 2 * acc[i][0]), bs4[0]);
            r.y = fmaf(sx * bk4[1], (float)(D_DIM - 2 * acc[i][1]), bs4[1]);
            r.z = fmaf(sx * bk4[2], (float)(D_DIM - 2 * acc[i][2]), bs4[2]);
            r.w = fmaf(sx * bk4[3], (float)(D_DIM - 2 * acc[i][3]), bs4[3]);
            *(float4*)(out + (size_t)(trow + i) * F_DIM + tcol) = r;
        }
    } else {
        // ================= imma group (cols 96..127) =================
        const int t = tid - 384;                     // 0..127
        const uint8_t* __restrict__ gA  = g_Xq + (size_t)t0 * D_DIM;
        const uint8_t* __restrict__ gBq = g_Kq + (size_t)(f0 + 96) * D_DIM;

        auto fillI = [&](int kt, int st) {
            const uint32_t base = sb + st * STG_I;
            const size_t gk = (size_t)kt * 256;
            #pragma unroll
            for (int i = 0; i < 16; ++i) {
                int idx = i * 128 + t;
                int sub = idx >> 10, r = (idx >> 3) & 127, c = (idx & 7) << 4;
                cp16(base + sub * 16384 + sw128(r * 128 + c),
                     gA + (size_t)r * D_DIM + gk + sub * 128 + c);
            }
            #pragma unroll
            for (int i = 0; i < 4; ++i) {
                int idx = i * 128 + t;
                int sub = idx >> 8, r = (idx >> 3) & 31, c = (idx & 7) << 4;
                cp16(base + OFF_B + sub * 4096 + sw128(r * 128 + c),
                     gBq + (size_t)r * D_DIM + gk + sub * 128 + c);
            }
            CP_COMMIT();
        };

        const int iw = wid - 12;
        const int wm = iw & 1, wn = iw >> 1;         // 2m x 2n, warp tile 64x16
        int acc[4][2][4];
        #pragma unroll
        for (int mi = 0; mi < 4; ++mi)
            #pragma unroll
            for (int ni = 0; ni < 2; ++ni)
                #pragma unroll
                for (int r = 0; r < 4; ++r) acc[mi][ni][r] = 0;

        const int arow = wm * 64 + (lane & 15);
        const int brow = wn * 16 + (lane & 15);
        const int khalf = (lane & 16);

        fillI(0, 0);
        for (int kt = 0; kt < 16; ++kt) {
            if (kt < 15) {
                fillI(kt + 1, (kt + 1) & 1);
                asm volatile("cp.async.wait_group 1;" ::: "memory");
            } else {
                asm volatile("cp.async.wait_group 0;" ::: "memory");
            }
            BAR_IMMA();
            const uint32_t stb = sb + (kt & 1) * STG_I;
            #pragma unroll
            for (int ks = 0; ks < 8; ++ks) {
                const int sub = ks >> 2;
                const int kcol = (ks & 3) * 32 + khalf;
                const uint32_t aSt = stb + sub * 16384;
                const uint32_t bSt = stb + OFF_B + sub * 4096;
                uint32_t b0, b1, b2, b3;
                ldsm4(b0, b1, b2, b3, bSt + sw128(brow * 128 + kcol));
                #pragma unroll
                for (int mi = 0; mi < 4; ++mi) {
                    uint32_t a0, a1, a2, a3;
                    ldsm4(a0, a1, a2, a3, aSt + sw128((arow + mi * 16) * 128 + kcol));
                    mma_s8(acc[mi][0], a0, a1, a2, a3, b0, b2);
                    mma_s8(acc[mi][1], a0, a1, a2, a3, b1, b3);
                }
            }
            BAR_IMMA();
        }

        const int lrow = lane >> 2;
        const int lcol = (lane & 3) * 2;
        const int rbase = t0 + wm * 64;
        const int cbase = f0 + 96 + wn * 16;
        #pragma unroll
        for (int mi = 0; mi < 4; ++mi) {
            float sx0 = 0.25f * g_bx[rbase + mi * 16 + lrow];
            float sx1 = 0.25f * g_bx[rbase + mi * 16 + lrow + 8];
            #pragma unroll
            for (int ni = 0; ni < 2; ++ni) {
                int c = cbase + ni * 8 + lcol;
                float k0v = g_bk[c], k1v = g_bk[c + 1];
                float b0v = bias[c], b1v = bias[c + 1];
                float2 v0, v1;
                v0.x = fmaf(sx0 * k0v, (float)acc[mi][ni][0], b0v);
                v0.y = fmaf(sx0 * k1v, (float)acc[mi][ni][1], b1v);
                v1.x = fmaf(sx1 * k0v, (float)acc[mi][ni][2], b0v);
                v1.y = fmaf(sx1 * k1v, (float)acc[mi][ni][3], b1v);
                *(float2*)(out + (size_t)(rbase + mi * 16 + lrow) * F_DIM + c) = v0;
                *(float2*)(out + (size_t)(rbase + mi * 16 + lrow + 8) * F_DIM + c) = v1;
            }
        }
    }
}

// ---------------------------------------------------------------------------
extern "C" void kernel_launch(void* const* d_in, const int* in_sizes, int n_in,
                              void* d_out, int out_size) {
    const float* x    = (const float*)d_in[0];
    const float* kern = (const float*)d_in[1];
    const float* bias = (const float*)d_in[2];
    float* out = (float*)d_out;

    pack_x_s8_kernel<<<M_TOK / 8, 256>>>(x);
    dim3 gk(F_DIM / 128, D_DIM / 128);
    pack_k_s8_kernel<<<gk, 256>>>(kern);
    reduce_bk_kernel<<<F_DIM / 256, 256>>>();

    cudaFuncSetAttribute(hybrid_dc_gemm,
                         cudaFuncAttributeMaxDynamicSharedMemorySize, SMEM_SZ);
    dim3 gg(F_DIM / 128, M_TOK / 128);
    hybrid_dc_gemm<<<gg, 512, SMEM_SZ>>>(bias, out);
}